// round 9
// baseline (speedup 1.0000x reference)
#include <cuda_runtime.h>
#include <cooperative_groups.h>

namespace cg = cooperative_groups;

// Problem constants
#define B_    128
#define T_    1024
#define H_    512
#define I_    64
#define KA    576              // augmented K = H + I
#define NCTA  128
#define NTHR  256
#define HT    32               // h-rows per CTA
#define BT    16               // b-cols per CTA
#define WS    68               // padded wdup k-stride: conflict-free stage, 16B-aligned reads
#define C1    0.9f             // 1 - dt/tau
#define C2    0.1f             // dt/tau

// floats: wdup[KA][WS] + stile[KA][BT] + hs[HT][BT] + red[2*NTHR]
#define SMEM_FLOATS (KA*WS + KA*BT + HT*BT + 2*NTHR)
#define SMEM_BYTES  (SMEM_FLOATS * 4)

// ---- global scratch (allocation-free rule: __device__ globals) ----
__device__ float g_S[2][H_ * B_];          // double-buffered sigmoid(h)

// packed f32x2 FMA (full-rate fp32 path on sm_103a)
__device__ __forceinline__ void fma2(unsigned long long &acc,
                                     unsigned long long a,
                                     unsigned long long b) {
    asm("fma.rn.f32x2 %0, %1, %2, %0;" : "+l"(acc) : "l"(a), "l"(b));
}

__device__ __forceinline__ float sigmoidf_(float x) {
    return 1.0f / (1.0f + __expf(-x));
}

__global__ void __launch_bounds__(NTHR, 1)
rnn_coop_kernel(const float* __restrict__ x,      // [B,T,I]
                const float* __restrict__ W_in,   // [H,I]
                const float* __restrict__ W_h,    // [H,H]
                const float* __restrict__ sigma,  // [H,T,B]
                const float* __restrict__ h0,     // [H,B]
                float* __restrict__ out)          // [B,T,H] ++ [H,B]
{
    extern __shared__ float sm[];
    float* wdup  = sm;                         // [KA][WS]  dup-pair weights
    float* stile = wdup + KA * WS;             // [KA][BT]  staged S (+x rows)
    float* hs    = stile + KA * BT;            // [HT][BT]  this CTA's h tile
    float* red   = hs + HT * BT;               // [2*NTHR]  K-split partials

    cg::grid_group grid = cg::this_grid();

    const int tid = threadIdx.x;
    const int cta = blockIdx.x;
    const int h0r = (cta >> 3) * HT;           // 16 h-tiles
    const int b0  = (cta & 7)  * BT;           // 8 b-tiles

    // ---- one-time: stage augmented weight slice into SMEM, duplicated pairs.
    // wdup[k][4j+{0,1}] = W[h0r+2j][k] ; wdup[k][4j+{2,3}] = W[h0r+2j+1][k]
    {
        const int KA4 = KA / 4;                // 144 float4 per W row
        #pragma unroll
        for (int i = 0; i < (KA4 * HT) / NTHR; ++i) {   // 18 iters
            int flat = i * NTHR + tid;
            int hl = flat / KA4;
            int k4 = flat % KA4;
            float4 w4;
            if (k4 < 128)
                w4 = *(const float4*)(W_h + (size_t)(h0r + hl) * H_ + 4 * k4);
            else
                w4 = *(const float4*)(W_in + (size_t)(h0r + hl) * I_ + (4 * k4 - 512));
            int j = hl >> 1, r = hl & 1;
            float* base = wdup + (size_t)(4 * k4) * WS + 4 * j + 2 * r;
            *(float2*)(base + 0 * WS) = make_float2(w4.x, w4.x);
            *(float2*)(base + 1 * WS) = make_float2(w4.y, w4.y);
            *(float2*)(base + 2 * WS) = make_float2(w4.z, w4.z);
            *(float2*)(base + 3 * WS) = make_float2(w4.w, w4.w);
        }
    }

    // ---- init h tile from h0, publish sigmoid(h0) into buffer 0
    #pragma unroll
    for (int i = 0; i < (HT * BT) / NTHR; ++i) {        // 2 iters
        int idx = i * NTHR + tid;
        int hl = idx / BT, bl = idx % BT;
        float h = h0[(size_t)(h0r + hl) * B_ + b0 + bl];
        hs[hl * BT + bl] = h;
        __stcg(&g_S[0][(size_t)(h0r + hl) * B_ + b0 + bl], sigmoidf_(h));
    }
    grid.sync();

    const int half = tid >> 7;                 // K-split half (0/1)
    const int sub  = tid & 127;
    const int hl2  = sub >> 3;                 // 0..15 (h-pair)
    const int blp  = sub & 7;                  // 0..7  (b-pair)

    int p = 0;
    for (int t = 0; t < T_; ++t) {
        // ---- stage S tile (rows 0..511) from global; .cg is REQUIRED:
        // L1 persists across steps within this launch and would serve stale S.
        {
            const float* Sg = g_S[p];
            #pragma unroll
            for (int i2 = 0; i2 < (H_ * BT) / 4 / NTHR; ++i2) {   // 8 iters
                int i = i2 * NTHR + tid;
                int k = i >> 2, c = (i & 3) * 4;
                float4 v = __ldcg((const float4*)(Sg + (size_t)k * B_ + b0 + c));
                *(float4*)(stile + k * BT + c) = v;
            }
        }
        // ---- stage x rows (transposed) into rows 512..575
        {
            int b  = tid >> 4;                 // 0..15
            int i4 = (tid & 15) * 4;           // 0..60
            float4 v = *(const float4*)(x + ((size_t)(b0 + b) * T_ + t) * I_ + i4);
            stile[(H_ + i4 + 0) * BT + b] = v.x;
            stile[(H_ + i4 + 1) * BT + b] = v.y;
            stile[(H_ + i4 + 2) * BT + b] = v.z;
            stile[(H_ + i4 + 3) * BT + b] = v.w;
        }
        __syncthreads();

        // ---- GEMM micro-kernel: 2h x 2b per thread, half of K each
        unsigned long long acc0 = 0ull, acc1 = 0ull;
        {
            const int kbeg = half * (KA / 2);
            const float* wp = wdup  + (size_t)kbeg * WS + 4 * hl2;
            const float* sp = stile + (size_t)kbeg * BT + 2 * blp;
            #pragma unroll 8
            for (int k = 0; k < KA / 2; ++k) {
                ulonglong2 w = *reinterpret_cast<const ulonglong2*>(wp);
                unsigned long long s = *reinterpret_cast<const unsigned long long*>(sp);
                fma2(acc0, w.x, s);
                fma2(acc1, w.y, s);
                wp += WS; sp += BT;
            }
        }

        // ---- reduce K-split partials through SMEM
        if (half) {
            ((unsigned long long*)red)[sub * 2 + 0] = acc0;
            ((unsigned long long*)red)[sub * 2 + 1] = acc1;
        }
        __syncthreads();

        if (half == 0) {
            unsigned long long o0 = ((const unsigned long long*)red)[sub * 2 + 0];
            unsigned long long o1 = ((const unsigned long long*)red)[sub * 2 + 1];
            float v00 = __uint_as_float((unsigned)acc0)         + __uint_as_float((unsigned)o0);
            float v01 = __uint_as_float((unsigned)(acc0 >> 32)) + __uint_as_float((unsigned)(o0 >> 32));
            float v10 = __uint_as_float((unsigned)acc1)         + __uint_as_float((unsigned)o1);
            float v11 = __uint_as_float((unsigned)(acc1 >> 32)) + __uint_as_float((unsigned)(o1 >> 32));

            int h = hl2 * 2, b = blp * 2;
            const float* sgp = sigma + ((size_t)(h0r + h) * T_ + t) * B_ + b0 + b;
            float2 s0 = *(const float2*)sgp;
            float2 s1 = *(const float2*)(sgp + (size_t)T_ * B_);

            float hn00 = C1 * hs[(h    ) * BT + b    ] + C2 * (v00 + s0.x);
            float hn01 = C1 * hs[(h    ) * BT + b + 1] + C2 * (v01 + s0.y);
            float hn10 = C1 * hs[(h + 1) * BT + b    ] + C2 * (v10 + s1.x);
            float hn11 = C1 * hs[(h + 1) * BT + b + 1] + C2 * (v11 + s1.y);

            hs[(h    ) * BT + b    ] = hn00;
            hs[(h    ) * BT + b + 1] = hn01;
            hs[(h + 1) * BT + b    ] = hn10;
            hs[(h + 1) * BT + b + 1] = hn11;
        }
        __syncthreads();

        // ---- epilogue: out tile + sigmoid into next S buffer (.cg publish)
        if (tid < 128) {
            int b = tid >> 3, hsg = (tid & 7) * 4;
            float4 v;
            v.x = hs[(hsg + 0) * BT + b];
            v.y = hs[(hsg + 1) * BT + b];
            v.z = hs[(hsg + 2) * BT + b];
            v.w = hs[(hsg + 3) * BT + b];
            *(float4*)(out + ((size_t)(b0 + b) * T_ + t) * H_ + h0r + hsg) = v;
        } else {
            int s2 = tid - 128;
            int hl = s2 >> 2, q = (s2 & 3) * 4;
            float4 v = *(const float4*)(hs + hl * BT + q);
            float4 sv;
            sv.x = sigmoidf_(v.x); sv.y = sigmoidf_(v.y);
            sv.z = sigmoidf_(v.z); sv.w = sigmoidf_(v.w);
            __stcg((float4*)(g_S[1 - p] + (size_t)(h0r + hl) * B_ + b0 + q), sv);
        }

        grid.sync();     // driver-managed grid barrier (execution + memory)
        p ^= 1;
    }

    // ---- h_last [H,B] appended after out [B,T,H]
    if (tid < 128) {
        int hl = tid >> 2, q = (tid & 3) * 4;
        float4 v = *(const float4*)(hs + hl * BT + q);
        *(float4*)(out + (size_t)B_ * T_ * H_ + (size_t)(h0r + hl) * B_ + b0 + q) = v;
    }
}

extern "C" void kernel_launch(void* const* d_in, const int* in_sizes, int n_in,
                              void* d_out, int out_size) {
    const float* x    = (const float*)d_in[0];
    const float* W_in = (const float*)d_in[1];
    const float* W_h  = (const float*)d_in[2];
    const float* sg   = (const float*)d_in[3];
    const float* h0   = (const float*)d_in[4];
    float* out = (float*)d_out;

    static int smem_set = 0;
    if (!smem_set) {
        cudaFuncSetAttribute(rnn_coop_kernel,
                             cudaFuncAttributeMaxDynamicSharedMemorySize, SMEM_BYTES);
        smem_set = 1;
    }

    cudaLaunchConfig_t cfg = {};
    cfg.gridDim  = dim3(NCTA, 1, 1);
    cfg.blockDim = dim3(NTHR, 1, 1);
    cfg.dynamicSmemBytes = SMEM_BYTES;
    cfg.stream = 0;
    cudaLaunchAttribute attr[1];
    attr[0].id = cudaLaunchAttributeCooperative;
    attr[0].val.cooperative = 1;
    cfg.attrs = attr;
    cfg.numAttrs = 1;

    cudaLaunchKernelEx(&cfg, rnn_coop_kernel, x, W_in, W_h, sg, h0, out);
}

// round 10
// speedup vs baseline: 1.7143x; 1.7143x over previous
#include <cuda_runtime.h>
#include <cooperative_groups.h>

namespace cg = cooperative_groups;

// Problem constants
#define B_    128
#define T_    1024
#define H_    512
#define I_    64
#define KA    576              // augmented K = H + I
#define NCTA  128
#define NTHR  256
#define HT    16               // h-rows per CTA
#define BT    32               // b-cols per CTA
#define C1    0.9f
#define C2    0.1f

// smem floats: wpk[KA][16] + hs[HT][BT] + red[8][8][32] f32x2
#define WPK_F   (KA * 16)          // 9216
#define HS_F    (HT * BT)          // 512
#define RED_F   (8 * 8 * 32 * 2)   // 4096
#define SMEM_FLOATS (WPK_F + HS_F + RED_F)
#define SMEM_BYTES  (SMEM_FLOATS * 4)

// ---- global scratch (__device__ globals: allocation-free rule) ----
__device__ float g_S[2][H_ * B_];          // double-buffered sigmoid(h)
__device__ float g_xT[T_ * I_ * B_];       // x transposed to [t][i][b]

__device__ __forceinline__ void fma2(unsigned long long &acc,
                                     unsigned long long a,
                                     unsigned long long b) {
    asm("fma.rn.f32x2 %0, %1, %2, %0;" : "+l"(acc) : "l"(a), "l"(b));
}

__device__ __forceinline__ float sigmoidf_(float x) {
    return 1.0f / (1.0f + __expf(-x));
}

__global__ void __launch_bounds__(NTHR, 1)
rnn_coop_kernel(const float* __restrict__ x,      // [B,T,I]
                const float* __restrict__ W_in,   // [H,I]
                const float* __restrict__ W_h,    // [H,H]
                const float* __restrict__ sigma,  // [H,T,B]
                const float* __restrict__ h0,     // [H,B]
                float* __restrict__ out)          // [B,T,H] ++ [H,B]
{
    extern __shared__ float sm[];
    float*  wpk  = sm;                     // [KA][16] interleaved W rows
    float*  hs   = sm + WPK_F;             // [HT][BT] h tile
    float2* redf = (float2*)(sm + WPK_F + HS_F);   // [8 hp][8 w][32 lane]
    float*  ts   = sm + WPK_F + HS_F;      // transpose tile alias (<= RED_F)

    cg::grid_group grid = cg::this_grid();

    const int tid  = threadIdx.x;
    const int warp = tid >> 5;
    const int lane = tid & 31;
    const int cta  = blockIdx.x;
    const int h0r  = (cta >> 2) * HT;      // 32 h-tiles
    const int b0   = (cta & 3)  * BT;      // 4 b-tiles

    // ---- one-time: stage interleaved weights wpk[k][j] = W_aug[h0r+j][k]
    {
        // 16 rows x 144 float4 = 2304 tasks
        #pragma unroll
        for (int i = 0; i < 9; ++i) {
            int idx = i * NTHR + tid;
            int j   = idx / 144;
            int k4  = idx % 144;
            float4 w4 = (k4 < 128)
                ? *(const float4*)(W_h  + (size_t)(h0r + j) * H_ + 4 * k4)
                : *(const float4*)(W_in + (size_t)(h0r + j) * I_ + 4 * k4 - 512);
            wpk[(4 * k4 + 0) * 16 + j] = w4.x;
            wpk[(4 * k4 + 1) * 16 + j] = w4.y;
            wpk[(4 * k4 + 2) * 16 + j] = w4.z;
            wpk[(4 * k4 + 3) * 16 + j] = w4.w;
        }
    }

    // ---- one-time: transpose x[B,T,I] -> g_xT[t][i][b] via 32x32 smem tiles
    // tiles: 4 b-blocks x 2 i-blocks x 1024 t = 8192; 64 per CTA
    for (int tile = cta; tile < 8192; tile += NCTA) {
        int tb = tile & 3;
        int ti = (tile >> 2) & 1;
        int tt = tile >> 3;
        {   // load + transpose into ts[i][b] (pad 33)
            int row = tid >> 3;            // b-row 0..31
            int c4  = tid & 7;             // i-quad 0..7
            float4 v = *(const float4*)(x + (size_t)(tb * 32 + row) * (T_ * I_)
                                          + (size_t)tt * I_ + ti * 32 + 4 * c4);
            ts[(4 * c4 + 0) * 33 + row] = v.x;
            ts[(4 * c4 + 1) * 33 + row] = v.y;
            ts[(4 * c4 + 2) * 33 + row] = v.z;
            ts[(4 * c4 + 3) * 33 + row] = v.w;
        }
        __syncthreads();
        {   // write coalesced
            int irow = tid >> 3;           // i-row 0..31
            int b4   = tid & 7;            // b-quad 0..7
            float4 v;
            v.x = ts[irow * 33 + 4 * b4 + 0];
            v.y = ts[irow * 33 + 4 * b4 + 1];
            v.z = ts[irow * 33 + 4 * b4 + 2];
            v.w = ts[irow * 33 + 4 * b4 + 3];
            __stcg((float4*)(g_xT + ((size_t)tt * I_ + ti * 32 + irow) * B_
                                  + tb * 32 + 4 * b4), v);
        }
        __syncthreads();
    }

    // ---- init h tile + publish sigmoid(h0) into buffer 0
    #pragma unroll
    for (int i = 0; i < (HT * BT) / NTHR; ++i) {
        int idx = i * NTHR + tid;
        int hl = idx >> 5, bl = idx & 31;
        float h = h0[(size_t)(h0r + hl) * B_ + b0 + bl];
        hs[hl * BT + bl] = h;
        __stcg(&g_S[0][(size_t)(h0r + hl) * B_ + b0 + bl], sigmoidf_(h));
    }
    grid.sync();

    const int hp = tid >> 5;               // update-phase h-pair (=warp)
    const int ub = lane;                   // update-phase b

    int p = 0;
    for (int t = 0; t < T_; ++t) {
        // prefetch sigma for the update phase (covers DRAM latency w/ GEMM)
        const float* sgp = sigma + ((size_t)(h0r + 2 * hp) * T_ + t) * B_ + b0 + ub;
        float sg0 = __ldg(sgp);
        float sg1 = __ldg(sgp + (size_t)T_ * B_);

        // ---- GEMM: warp covers 16h x 32b, K-split 8 (64 S-k + 8 x-k each)
        unsigned long long acc[8];
        #pragma unroll
        for (int i = 0; i < 8; ++i) acc[i] = 0ull;

        {   // S part: k in [64*warp, 64*warp+64)
            const float* sp = g_S[p] + (size_t)(64 * warp) * B_ + b0 + lane;
            const float* wq = wpk + (64 * warp) * 16;
            float pre[8];
            #pragma unroll
            for (int j = 0; j < 8; ++j) pre[j] = __ldcg(sp + j * B_);
            #pragma unroll
            for (int kk = 0; kk < 64; kk += 8) {
                float cur[8];
                #pragma unroll
                for (int j = 0; j < 8; ++j) cur[j] = pre[j];
                if (kk < 56) {
                    const float* spn = sp + (size_t)(kk + 8) * B_;
                    #pragma unroll
                    for (int j = 0; j < 8; ++j) pre[j] = __ldcg(spn + j * B_);
                }
                #pragma unroll
                for (int j = 0; j < 8; ++j) {
                    unsigned long long sd;
                    asm("mov.b64 %0, {%1, %1};" : "=l"(sd) : "f"(cur[j]));
                    const ulonglong2* w2 = (const ulonglong2*)(wq + (kk + j) * 16);
                    ulonglong2 wa = w2[0], wb = w2[1], wc = w2[2], wd = w2[3];
                    fma2(acc[0], wa.x, sd); fma2(acc[1], wa.y, sd);
                    fma2(acc[2], wb.x, sd); fma2(acc[3], wb.y, sd);
                    fma2(acc[4], wc.x, sd); fma2(acc[5], wc.y, sd);
                    fma2(acc[6], wd.x, sd); fma2(acc[7], wd.y, sd);
                }
            }
        }
        {   // x part: kx in [8*warp, 8*warp+8)
            const float* xp = g_xT + ((size_t)t * I_ + 8 * warp) * B_ + b0 + lane;
            const float* wq = wpk + (512 + 8 * warp) * 16;
            float xv[8];
            #pragma unroll
            for (int j = 0; j < 8; ++j) xv[j] = __ldcg(xp + j * B_);
            #pragma unroll
            for (int j = 0; j < 8; ++j) {
                unsigned long long sd;
                asm("mov.b64 %0, {%1, %1};" : "=l"(sd) : "f"(xv[j]));
                const ulonglong2* w2 = (const ulonglong2*)(wq + j * 16);
                ulonglong2 wa = w2[0], wb = w2[1], wc = w2[2], wd = w2[3];
                fma2(acc[0], wa.x, sd); fma2(acc[1], wa.y, sd);
                fma2(acc[2], wb.x, sd); fma2(acc[3], wb.y, sd);
                fma2(acc[4], wc.x, sd); fma2(acc[5], wc.y, sd);
                fma2(acc[6], wd.x, sd); fma2(acc[7], wd.y, sd);
            }
        }

        // ---- store K-split partials: red[hp][warp][lane], conflict-free
        #pragma unroll
        for (int h = 0; h < 8; ++h) {
            float2 v;
            v.x = __uint_as_float((unsigned)acc[h]);
            v.y = __uint_as_float((unsigned)(acc[h] >> 32));
            redf[(h * 8 + warp) * 32 + lane] = v;
        }
        __syncthreads();

        // ---- sum 8 partials + leaky update (thread: hp = tid>>5, b = lane)
        {
            float gx = 0.f, gy = 0.f;
            #pragma unroll
            for (int w = 0; w < 8; ++w) {
                float2 v = redf[(hp * 8 + w) * 32 + ub];
                gx += v.x; gy += v.y;
            }
            int hA = 2 * hp, hB = 2 * hp + 1;
            float hn0 = C1 * hs[hA * BT + ub] + C2 * (gx + sg0);
            float hn1 = C1 * hs[hB * BT + ub] + C2 * (gy + sg1);
            hs[hA * BT + ub] = hn0;
            hs[hB * BT + ub] = hn1;
            __stcg(&g_S[1 - p][(size_t)(h0r + hA) * B_ + b0 + ub], sigmoidf_(hn0));
            __stcg(&g_S[1 - p][(size_t)(h0r + hB) * B_ + b0 + ub], sigmoidf_(hn1));
        }
        __syncthreads();

        // ---- coalesced out tile [B,T,H]
        if (tid < 128) {
            int bb = tid >> 2, hq = (tid & 3) * 4;
            float4 v;
            v.x = hs[(hq + 0) * BT + bb];
            v.y = hs[(hq + 1) * BT + bb];
            v.z = hs[(hq + 2) * BT + bb];
            v.w = hs[(hq + 3) * BT + bb];
            *(float4*)(out + ((size_t)(b0 + bb) * T_ + t) * H_ + h0r + hq) = v;
        }

        grid.sync();
        p ^= 1;
    }

    // ---- h_last [H,B] appended after out [B,T,H]
    if (tid < 128) {
        int hl = tid >> 3, q = (tid & 7) * 4;
        float4 v = *(const float4*)(hs + hl * BT + q);
        *(float4*)(out + (size_t)B_ * T_ * H_ + (size_t)(h0r + hl) * B_ + b0 + q) = v;
    }
}

extern "C" void kernel_launch(void* const* d_in, const int* in_sizes, int n_in,
                              void* d_out, int out_size) {
    const float* x    = (const float*)d_in[0];
    const float* W_in = (const float*)d_in[1];
    const float* W_h  = (const float*)d_in[2];
    const float* sg   = (const float*)d_in[3];
    const float* h0   = (const float*)d_in[4];
    float* out = (float*)d_out;

    static int smem_set = 0;
    if (!smem_set) {
        cudaFuncSetAttribute(rnn_coop_kernel,
                             cudaFuncAttributeMaxDynamicSharedMemorySize, SMEM_BYTES);
        smem_set = 1;
    }

    cudaLaunchConfig_t cfg = {};
    cfg.gridDim  = dim3(NCTA, 1, 1);
    cfg.blockDim = dim3(NTHR, 1, 1);
    cfg.dynamicSmemBytes = SMEM_BYTES;
    cfg.stream = 0;
    cudaLaunchAttribute attr[1];
    attr[0].id = cudaLaunchAttributeCooperative;
    attr[0].val.cooperative = 1;
    cfg.attrs = attr;
    cfg.numAttrs = 1;

    cudaLaunchKernelEx(&cfg, rnn_coop_kernel, x, W_in, W_h, sg, h0, out);
}